// round 15
// baseline (speedup 1.0000x reference)
#include <cuda_runtime.h>
#include <cuda_fp16.h>
#include <cuda_bf16.h>
#include <cstdint>

// Int8Linear: out[M,N] f32 = (x[M,K] i8 @ w[K,N] i8).s32 + bias[N] f16
// M=16384, K=2048, N=2048. Harness materializes x/w as INT32.
//
// R13: cg2 (2-CTA cluster) 512x256 tiles. In cta_group::2, B is split N/2 per
// CTA -> B loaded once per PAIR: fills drop 1024MB -> 768MB (L2-bound kernel).
//   prep:  x int32 -> g_Xb bf16 ; W int32 [K,N] -> g_Wt bf16 [N,K]
//   gemm:  pair computes 512x256 via two cg2 M=256 accumulators (512 TMEM
//          cols/CTA), 4-stage cp.async pipeline (48KB/stage/CTA), SW128.

#if defined(__CUDA_ARCH__) && (defined(__CUDA_ARCH_FEAT_SM103_ALL) || defined(__CUDA_ARCH_FEAT_SM100_ALL))
#define HAS_TCGEN05 1
#else
#define HAS_TCGEN05 0
#endif

#define MDIM 16384
#define NDIM 2048
#define KDIM 2048
#define BM 512                 // per pair
#define BN 256
#define BKE 64                 // K elems per iter (128 bytes bf16)
#define BKB 128
#define STAGES 4
#define K_ITERS (KDIM / BKE)   // 32
#define KROWB (KDIM * 2)       // bytes per bf16 K-row
#define A_BYTES 32768          // 256 rows x 128B per CTA per stage
#define B_BYTES 16384          // 128 rows x 128B per CTA per stage
#define STAGE_BYTES (A_BYTES + B_BYTES)   // 49152
#define SMEM_DYN (2048 + STAGES * STAGE_BYTES)

__device__ __align__(32) __nv_bfloat16 g_Xb[(size_t)MDIM * KDIM];  // 64 MB
__device__ __align__(32) __nv_bfloat16 g_Wt[(size_t)NDIM * KDIM];  // 8 MB

// ---------------- helpers ----------------
__device__ __forceinline__ uint32_t smem_u32(const void* p) {
    uint32_t a;
    asm("{ .reg .u64 t; cvta.to.shared.u64 t, %1; cvt.u32.u64 %0, t; }"
        : "=r"(a) : "l"(p));
    return a;
}
__device__ __forceinline__ uint32_t swz128(uint32_t off) {
    return off ^ ((off >> 3) & 0x70);
}
__device__ __forceinline__ void cp_async16(uint32_t dst, const void* src) {
    asm volatile("cp.async.cg.shared.global [%0], [%1], 16;" :: "r"(dst), "l"(src));
}
__device__ __forceinline__ void cp_commit() {
    asm volatile("cp.async.commit_group;" ::: "memory");
}
__device__ __forceinline__ void cp_wait2() {
    asm volatile("cp.async.wait_group 2;" ::: "memory");
}
__device__ __forceinline__ void mbar_init(uint32_t addr, uint32_t cnt) {
    asm volatile("mbarrier.init.shared.b64 [%0], %1;" :: "r"(addr), "r"(cnt) : "memory");
}
__device__ __forceinline__ void mbar_wait(uint32_t addr, uint32_t parity) {
    asm volatile(
        "{\n\t.reg .pred P;\nW_%=:\n\t"
        "mbarrier.try_wait.parity.acquire.cta.shared::cta.b64 P, [%0], %1, 0x989680;\n\t"
        "@!P bra W_%=;\n\t}"
        :: "r"(addr), "r"(parity) : "memory");
}
__device__ __forceinline__ void mbar_wait_clu(uint32_t addr, uint32_t parity) {
    asm volatile(
        "{\n\t.reg .pred P;\nWc_%=:\n\t"
        "mbarrier.try_wait.parity.acquire.cluster.shared::cta.b64 P, [%0], %1, 0x989680;\n\t"
        "@!P bra Wc_%=;\n\t}"
        :: "r"(addr), "r"(parity) : "memory");
}
__device__ __forceinline__ void mbar_arrive_local(uint32_t addr) {
    asm volatile("mbarrier.arrive.shared.b64 _, [%0];" :: "r"(addr) : "memory");
}
__device__ __forceinline__ void mbar_arrive_rank0(uint32_t addr) {
    asm volatile(
        "{\n\t.reg .b32 rem;\n\t"
        "mapa.shared::cluster.u32 rem, %0, 0;\n\t"
        "mbarrier.arrive.shared::cluster.b64 _, [rem];\n\t}"
        :: "r"(addr) : "memory");
}

#if HAS_TCGEN05
// K-major SW128 smem descriptor: layout=SW128(2), version=1, SBO=64, LBO=1
__device__ __forceinline__ uint64_t make_desc_sw128(uint32_t addr) {
    return (2ull << 61) | (1ull << 46) | (64ull << 32) | (1ull << 16)
         | (uint64_t)((addr >> 4) & 0x3FFF);
}
// cg2 kind::f16 (bf16 in, f32 accum), SS form.
__device__ __forceinline__ void mma_bf16_cg2(uint32_t d, uint64_t ad, uint64_t bd,
                                             uint32_t idesc, uint32_t en) {
    asm volatile(
        "{\n\t.reg .pred p;\n\t"
        "setp.ne.u32 p, %5, 0;\n\t"
        "tcgen05.mma.cta_group::2.kind::f16 [%0], %1, %2, %3, "
        "{%4, %4, %4, %4, %4, %4, %4, %4}, p;\n\t}"
        :: "r"(d), "l"(ad), "l"(bd), "r"(idesc), "r"(0u), "r"(en) : "memory");
}
__device__ __forceinline__ void ldtm32(uint32_t addr, uint32_t* r) {
    asm volatile(
        "tcgen05.ld.sync.aligned.32x32b.x32.b32 "
        "{%0, %1, %2, %3, %4, %5, %6, %7, "
        " %8, %9, %10, %11, %12, %13, %14, %15, "
        " %16, %17, %18, %19, %20, %21, %22, %23, "
        " %24, %25, %26, %27, %28, %29, %30, %31}, [%32];"
        : "=r"(r[0]),  "=r"(r[1]),  "=r"(r[2]),  "=r"(r[3]),
          "=r"(r[4]),  "=r"(r[5]),  "=r"(r[6]),  "=r"(r[7]),
          "=r"(r[8]),  "=r"(r[9]),  "=r"(r[10]), "=r"(r[11]),
          "=r"(r[12]), "=r"(r[13]), "=r"(r[14]), "=r"(r[15]),
          "=r"(r[16]), "=r"(r[17]), "=r"(r[18]), "=r"(r[19]),
          "=r"(r[20]), "=r"(r[21]), "=r"(r[22]), "=r"(r[23]),
          "=r"(r[24]), "=r"(r[25]), "=r"(r[26]), "=r"(r[27]),
          "=r"(r[28]), "=r"(r[29]), "=r"(r[30]), "=r"(r[31])
        : "r"(addr));
}
#endif

// ---------------- prep: x convert + W transpose/convert, one kernel ----------------
// blocks [0, 16384): convert x (8 elems/thread). blocks [16384, 16640): transpose.
#define CONV_BLOCKS ((MDIM * KDIM) / 8 / 256)   // 16384
__global__ void __launch_bounds__(256) prep_kernel(const int* __restrict__ x,
                                                   const int* __restrict__ W) {
    __shared__ __nv_bfloat16 t[128][136];
    int bid = blockIdx.x;
    int tid = threadIdx.x;
    if (bid < CONV_BLOCKS) {
        size_t tt = (size_t)bid * 256 + tid;
        const int4* src = reinterpret_cast<const int4*>(x) + tt * 2;
        int4 v0 = src[0];
        int4 v1 = src[1];
        __nv_bfloat162 o[4];
        o[0] = __nv_bfloat162(__int2bfloat16_rn(v0.x), __int2bfloat16_rn(v0.y));
        o[1] = __nv_bfloat162(__int2bfloat16_rn(v0.z), __int2bfloat16_rn(v0.w));
        o[2] = __nv_bfloat162(__int2bfloat16_rn(v1.x), __int2bfloat16_rn(v1.y));
        o[3] = __nv_bfloat162(__int2bfloat16_rn(v1.z), __int2bfloat16_rn(v1.w));
        *reinterpret_cast<uint4*>(g_Xb + tt * 8) = *reinterpret_cast<uint4*>(o);
        return;
    }
    int tb = bid - CONV_BLOCKS;                 // 0..255
    int nb = (tb & 15) * 128;
    int kb = (tb >> 4) * 128;
    #pragma unroll
    for (int i = 0; i < 16; i++) {
        int idx = tid + i * 256;
        int r = idx >> 5, c4 = idx & 31;
        int4 v = *reinterpret_cast<const int4*>(
            W + (size_t)(kb + r) * NDIM + nb + c4 * 4);
        t[r][c4 * 4 + 0] = __int2bfloat16_rn(v.x);
        t[r][c4 * 4 + 1] = __int2bfloat16_rn(v.y);
        t[r][c4 * 4 + 2] = __int2bfloat16_rn(v.z);
        t[r][c4 * 4 + 3] = __int2bfloat16_rn(v.w);
    }
    __syncthreads();
    #pragma unroll
    for (int i = 0; i < 8; i++) {
        int idx = tid + i * 256;
        int n = idx >> 4, j8 = idx & 15;
        __nv_bfloat16 buf[8];
        #pragma unroll
        for (int b = 0; b < 8; b++) buf[b] = t[j8 * 8 + b][n];
        *reinterpret_cast<uint4*>(g_Wt + (size_t)(nb + n) * KDIM + kb + j8 * 8) =
            *reinterpret_cast<uint4*>(buf);
    }
}

// ---------------- cg2 GEMM ----------------
__global__ void __launch_bounds__(256, 1) __cluster_dims__(2, 1, 1)
gemm_kernel(const __half* __restrict__ bias, float* __restrict__ out) {
#if HAS_TCGEN05
    extern __shared__ char smem[];
    uint32_t sb     = smem_u32(smem);
    uint32_t mdone  = sb;            // 4 x 8B (multicast commit targets, per CTA)
    uint32_t mfull  = sb + 64;       // 4 x 8B (leader only, count=2)
    uint32_t tptr   = sb + 128;
    uint32_t tiles  = (sb + 1024) & ~1023u;

    int tid  = threadIdx.x;
    int wid  = tid >> 5;
    int lane = tid & 31;
    int rank = blockIdx.x & 1;               // cluster rank (cluster dim x=2)
    int m0 = blockIdx.y * BM;
    int n0 = (blockIdx.x >> 1) * BN;

    if (wid == 0) {
        asm volatile("tcgen05.alloc.cta_group::2.sync.aligned.shared::cta.b32 [%0], 512;"
                     :: "r"(tptr) : "memory");
        asm volatile("tcgen05.relinquish_alloc_permit.cta_group::2.sync.aligned;");
    }
    if (tid == 0) {
        #pragma unroll
        for (int s = 0; s < STAGES; s++) {
            mbar_init(mdone + s * 8, 1);
            mbar_init(mfull + s * 8, 2);
        }
    }
    __syncthreads();
    uint32_t tmem;
    asm volatile("ld.shared.b32 %0, [%1];" : "=r"(tmem) : "r"(tptr));

    // Per-thread fixed row pointers + swizzled dst offsets (12 chunks of 16B).
    // rows 0..127:   A half of acc0 -> g_Xb row m0 + rank*128 + row
    // rows 128..255: A half of acc1 -> g_Xb row m0 + 256 + rank*128 + row-128
    // rows 256..383: B half         -> g_Wt row n0 + rank*128 + row-256
    const char* rowp[12];
    uint32_t dstoff[12];
    {
        const char* xb = reinterpret_cast<const char*>(g_Xb);
        const char* wt = reinterpret_cast<const char*>(g_Wt);
        #pragma unroll
        for (int i = 0; i < 12; i++) {
            int idx = tid + i * 256;
            int row = idx >> 3, part = idx & 7;
            dstoff[i] = swz128((uint32_t)(row * 128 + part * 16));
            size_t g;
            const char* base;
            if (row < 128)       { g = (size_t)(m0 + rank * 128 + row);        base = xb; }
            else if (row < 256)  { g = (size_t)(m0 + 256 + rank * 128 + row - 128); base = xb; }
            else                 { g = (size_t)(n0 + rank * 128 + row - 256);  base = wt; }
            rowp[i] = base + g * KROWB + part * 16;
        }
    }
    auto load_stage = [&](uint32_t stBase, int kOff) {
        #pragma unroll
        for (int i = 0; i < 12; i++)
            cp_async16(stBase + dstoff[i], rowp[i] + kOff);
    };

    // Prologue: stages 0..2
    load_stage(tiles + 0 * STAGE_BYTES, 0 * BKB); cp_commit();
    load_stage(tiles + 1 * STAGE_BYTES, 1 * BKB); cp_commit();
    load_stage(tiles + 2 * STAGE_BYTES, 2 * BKB); cp_commit();

    // Cluster sync: mbarriers + TMEM alloc visible before any cross-CTA arrive.
    asm volatile("barrier.cluster.arrive.aligned;" ::: "memory");
    asm volatile("barrier.cluster.wait.aligned;" ::: "memory");

    const uint32_t idesc = (1u << 4) | (1u << 7) | (1u << 10)
                         | ((BN / 8) << 17) | ((256 / 16) << 24);   // M=256, N=256
    int phD[STAGES] = {0, 0, 0, 0};
    int phF[STAGES] = {0, 0, 0, 0};

    for (int k = 0; k < K_ITERS; k++) {
        int s = k & 3;
        cp_wait2();                 // stage k data (group k) complete locally
        __syncthreads();
        if (tid == 0) {
            asm volatile("fence.proxy.async;" ::: "memory");
            if (rank == 0) mbar_arrive_local(mfull + s * 8);
            else           mbar_arrive_rank0(mfull + s * 8);
        }
        if (rank == 0 && tid == 0) {
            mbar_wait_clu(mfull + s * 8, phF[s]);
            phF[s] ^= 1;
            uint32_t stb = tiles + s * STAGE_BYTES;
            uint64_t a0 = make_desc_sw128(stb);
            uint64_t a1 = make_desc_sw128(stb + 16384);
            uint64_t bd = make_desc_sw128(stb + A_BYTES);
            #pragma unroll
            for (int st = 0; st < 4; st++) {    // 4 x K=16 bf16 steps per 128B
                uint32_t en = (k > 0 || st > 0) ? 1u : 0u;
                mma_bf16_cg2(tmem,       a0 + st * 2, bd + st * 2, idesc, en);
                mma_bf16_cg2(tmem + 256, a1 + st * 2, bd + st * 2, idesc, en);
            }
            asm volatile(
                "tcgen05.commit.cta_group::2.mbarrier::arrive::one.shared::cluster"
                ".multicast::cluster.b64 [%0], %1;"
                :: "r"(mdone + s * 8), "h"((uint16_t)3) : "memory");
        }
        if (k >= 1) {               // stage to refill = (k+3)%4 = (k-1)%4
            int ws = (k - 1) & 3;
            mbar_wait(mdone + ws * 8, phD[ws]);
            phD[ws] ^= 1;
        }
        int nk = k + 3;
        if (nk < K_ITERS) load_stage(tiles + (nk & 3) * STAGE_BYTES, nk * BKB);
        cp_commit();                // uniform group count
    }
    {
        int sl = (K_ITERS - 1) & 3;
        mbar_wait(mdone + sl * 8, phD[sl]);
    }
    asm volatile("tcgen05.fence::after_thread_sync;" ::: "memory");

    // Epilogue: warps 0-3 -> acc0 (cols 0-255), warps 4-7 -> acc1 (cols 256-511).
    // CTA rank r holds D rows r*128..+127 of each 256-row accumulator.
    int wg = wid >> 2;
    int wlocal = wid & 3;
    uint32_t dt = tmem + wg * 256;
    int m = m0 + wg * 256 + rank * 128 + wlocal * 32 + lane;
    float* orow = out + (size_t)m * NDIM + n0;
    #pragma unroll 1
    for (int ch = 0; ch < 8; ch++) {
        uint32_t r[32];
        ldtm32(dt + ch * 32, r);
        asm volatile("tcgen05.wait::ld.sync.aligned;" ::: "memory");
        int nb = n0 + ch * 32;
        #pragma unroll
        for (int c = 0; c < 32; c += 4) {
            float4 v;
            v.x = __uint_as_float(r[c + 0]) + __half2float(__ldg(bias + nb + c + 0));
            v.y = __uint_as_float(r[c + 1]) + __half2float(__ldg(bias + nb + c + 1));
            v.z = __uint_as_float(r[c + 2]) + __half2float(__ldg(bias + nb + c + 2));
            v.w = __uint_as_float(r[c + 3]) + __half2float(__ldg(bias + nb + c + 3));
            *reinterpret_cast<float4*>(orow + ch * 32 + c) = v;
        }
    }

    __syncthreads();
    if (wid == 0) {
        asm volatile("tcgen05.dealloc.cta_group::2.sync.aligned.b32 %0, 512;" :: "r"(tmem));
    }
    asm volatile("barrier.cluster.arrive.aligned;" ::: "memory");
    asm volatile("barrier.cluster.wait.aligned;" ::: "memory");
#else
    (void)bias; (void)out;
#endif
}

// ---------------- launch ----------------
extern "C" void kernel_launch(void* const* d_in, const int* in_sizes, int n_in,
                              void* d_out, int out_size) {
    (void)in_sizes; (void)n_in; (void)out_size;
    const int* x       = (const int*)d_in[0];     // int32 (promoted int8)
    const int* w       = (const int*)d_in[1];     // int32
    const __half* bias = (const __half*)d_in[2];  // zeros
    float* out         = (float*)d_out;

    cudaFuncSetAttribute(gemm_kernel, cudaFuncAttributeMaxDynamicSharedMemorySize, SMEM_DYN);

    prep_kernel<<<CONV_BLOCKS + 256, 256>>>(x, w);
    // grid.x = 2 CTAs/pair * 8 n-tiles, grid.y = 32 m-tiles (BM=512 per pair)
    gemm_kernel<<<dim3(16, 32), 256, SMEM_DYN>>>(bias, out);
}